// round 17
// baseline (speedup 1.0000x reference)
#include <cuda_runtime.h>
#include <cuda_fp16.h>
#include <math.h>
#include <stdint.h>

// ---------------- packed fp16 weights (all fragment-ordered for direct LDG) ----
// g_w2: [m4][nq4][kt32][nw4][grp2][lane32][4 halves]
// g_w1: [m4][w8][pq4][lane32][8 halves]   (k10 = b1 folded)
// g_hd: [m4][nq4][nw4][q2][tp2][lane32][4 halves]
__device__ __align__(16) __half g_w2[1048576];
__device__ __align__(16) __half g_w1[32768];
__device__ __align__(16) __half g_hd[65536];
// head sums: [g (9)][sample (32768)][22] f32 — written once per (g, block) CTA
__device__ float g_part[9 * 32768 * 22];

struct PM {
  const float *tokens;
  const float *ent_b2, *pad_b2;
};
struct PE {
  const float *tokens;
  const float *ent_bpos, *ent_bc, *ent_bv;
  const float *b_bpos, *b_bc, *b_bv;
  const float *gs_W, *gs_b;
  float *out;
};

__global__ void pack_kernel(const float* eW2, const float* pW2,
                            const float* eW1, const float* eb1,
                            const float* pW1, const float* pb1,
                            const float* eWpos, const float* eWc, const float* eWv,
                            const float* bWpos, const float* bWc, const float* bWv,
                            const float* attnW) {
  int tid = blockIdx.x * blockDim.x + threadIdx.x;
  int NT = gridDim.x * blockDim.x;
  for (int idx = tid; idx < 4 * 512 * 512; idx += NT) {
    int m = idx >> 18, r = idx & 262143, k = r >> 9, n = r & 511;
    float v = (m < 3) ? eW2[m * 262144 + k * 512 + n] : pW2[k * 512 + n];
    int nq = n >> 7, nl = n & 127;
    int nw = nl >> 5, nt = (nl >> 3) & 3;
    int grp = nt >> 1, odd = nt & 1;
    int kt = k >> 4, kk = k & 15;
    int lane = (nl & 7) * 4 + ((kk & 7) >> 1);
    int dst = ((((m * 4 + nq) * 32 + kt) * 4 + nw) * 2 + grp) * 256 +
              lane * 8 + odd * 4 + ((kk >> 3) & 1) * 2 + (kk & 1);
    g_w2[dst] = __float2half(v);
  }
  for (int idx = tid; idx < 4 * 512 * 16; idx += NT) {
    int m = idx >> 13, r = idx & 8191, n = r >> 4, k = r & 15;
    float v = 0.f;
    if (k < 10)       v = (m < 3) ? eW1[m * 5120 + k * 512 + n] : pW1[k * 512 + n];
    else if (k == 10) v = (m < 3) ? eb1[m * 512 + n] : pb1[n];
    int w = n >> 6, pq = (n >> 4) & 3, odd = (n >> 3) & 1;
    int lane = (n & 7) * 4 + ((k & 7) >> 1);
    int dst = ((m * 8 + w) * 4 + pq) * 256 + lane * 8 + odd * 4 + ((k >> 3) & 1) * 2 + (k & 1);
    g_w1[dst] = __float2half(v);
  }
  for (int idx = tid; idx < 4 * 32 * 512; idx += NT) {
    int m = idx >> 14, r = idx & 16383, n = r >> 9, k = r & 511;
    float v = 0.f;
    if (m < 3) {
      if (n < 3)       v = eWpos[m * 1536 + k * 3 + n];
      else if (n < 12) v = eWc[m * 4608 + k * 9 + (n - 3)];
      else if (n < 21) v = eWv[m * 4608 + k * 9 + (n - 12)];
    } else {
      if (n < 3)       v = bWpos[k * 3 + n];
      else if (n < 12) v = bWc[k * 9 + (n - 3)];
      else if (n < 21) v = bWv[k * 9 + (n - 12)];
      else if (n == 21) v = attnW[k];
    }
    int nq = k >> 7, kl = k & 127;
    int nw = kl >> 5, q = (kl >> 4) & 1, kk = kl & 15;
    int tp = n >> 4, odd = (n >> 3) & 1;
    int lane = (n & 7) * 4 + ((kk & 7) >> 1);
    int dst = ((((m * 4 + nq) * 4 + nw) * 2 + q) * 2 + tp) * 256 +
              lane * 8 + odd * 4 + ((kk >> 3) & 1) * 2 + (kk & 1);
    g_hd[dst] = __float2half(v);
  }
}

// ---------------- mma helpers ----------------
__device__ __forceinline__ void ldsm4(uint32_t a, uint32_t& r0, uint32_t& r1,
                                      uint32_t& r2, uint32_t& r3) {
  asm volatile("ldmatrix.sync.aligned.m8n8.x4.shared.b16 {%0,%1,%2,%3}, [%4];"
               : "=r"(r0), "=r"(r1), "=r"(r2), "=r"(r3) : "r"(a));
}
__device__ __forceinline__ void mma16816(float* c, uint32_t a0, uint32_t a1,
                                         uint32_t a2, uint32_t a3,
                                         uint32_t b0, uint32_t b1) {
  asm volatile(
      "mma.sync.aligned.m16n8k16.row.col.f32.f16.f16.f32 "
      "{%0,%1,%2,%3},{%4,%5,%6,%7},{%8,%9},{%0,%1,%2,%3};"
      : "+f"(c[0]), "+f"(c[1]), "+f"(c[2]), "+f"(c[3])
      : "r"(a0), "r"(a1), "r"(a2), "r"(a3), "r"(b0), "r"(b1));
}
__device__ __forceinline__ uint32_t packrelu(float a, float b) {
  __half2 h = __floats2half2_rn(fmaxf(a, 0.f), fmaxf(b, 0.f));
  return *(uint32_t*)&h;
}
__device__ __forceinline__ uint32_t packh2(float a, float b) {
  __half2 h = __floats2half2_rn(a, b);
  return *(uint32_t*)&h;
}
__device__ __forceinline__ int swA(int row, int kbyte) {
  return (row * 1024 + kbyte) ^ ((row & 7) << 4);
}

// ---------------- smem layout ----------------
#define NTH 256
static constexpr int OF_A  = 0;        // h1 tile: 64 rows x 1024B swizzled = 65,536
static constexpr int OF_P  = 65536;    // s_part 64 x 24 f32 = 6,144
static constexpr int SMEM_SZ = 71680;  // 70 KB -> 3 CTAs/SM

__device__ __forceinline__ float softplusf(float x) { return (x > 20.f) ? x : log1pf(expf(x)); }

__global__ void __launch_bounds__(NTH, 3) spectral_mma_kernel(PM p) {
  extern __shared__ __align__(128) unsigned char sm[];
  const uint32_t smb = (uint32_t)__cvta_generic_to_shared(sm);
  const int t = threadIdx.x, wid = t >> 5, lane = t & 31;
  const int g = blockIdx.y;
  const int m = (g < 3) ? g : 3;
  const int s0 = blockIdx.x * 64;
  const int mw = wid & 1, nw = wid >> 1;                // 2 M-warps x 4 N-warps (64x128)
  const int ag_r = ((lane >> 3) & 1) * 8 + (lane & 7);
  const int ag_k = ((lane >> 4) & 1) * 8;
  const int lr = lane >> 2, lc2 = (lane & 3) * 2;

  // ---- zero s_part (ordered before use by the h1 barrier below) ----
  for (int i = t; i < 64 * 24; i += NTH) ((float*)(sm + OF_P))[i] = 0.f;

  // ---- early-issue nq=0 B fragments (independent of phase A) ----
  const char* wbase0 = (const char*)g_w2 + (size_t)(m * 4) * 131072 + nw * 1024 + lane * 16;
  uint4 pb0 = *(const uint4*)(wbase0);
  uint4 pb1 = *(const uint4*)(wbase0 + 512);

  // ---- phase A: x A-frags DIRECT from global (no staging, no barrier) ----
  {
    // xa[mt]: rows mt*16+lr / +8, k-pairs lc2 / lc2+8 ; k<10 real, k==10 -> 1 (bias), else 0
    auto xv = [&](int row, int k) -> float {
      if (k < 10) return p.tokens[(size_t)(s0 + row) * 100 + g * 10 + k];
      return (k == 10) ? 1.f : 0.f;
    };
    uint32_t xa[4][4];
#pragma unroll
    for (int mt = 0; mt < 4; ++mt) {
      int r0 = mt * 16 + lr;
      xa[mt][0] = packh2(xv(r0, lc2),         xv(r0, lc2 + 1));
      xa[mt][1] = packh2(xv(r0 + 8, lc2),     xv(r0 + 8, lc2 + 1));
      xa[mt][2] = packh2(xv(r0, lc2 + 8),     xv(r0, lc2 + 9));
      xa[mt][3] = packh2(xv(r0 + 8, lc2 + 8), xv(r0 + 8, lc2 + 9));
    }
    const uint4* w1f = (const uint4*)((const char*)g_w1 + (size_t)(m * 8 + wid) * 2048) + lane;
#pragma unroll
    for (int pq = 0; pq < 4; ++pq) {
      uint4 bf = w1f[pq * 32];
      float pa[4][2][4];
#pragma unroll
      for (int mt = 0; mt < 4; ++mt) {
#pragma unroll
        for (int tn = 0; tn < 2; ++tn)
#pragma unroll
          for (int i = 0; i < 4; ++i) pa[mt][tn][i] = 0.f;
        mma16816(pa[mt][0], xa[mt][0], xa[mt][1], xa[mt][2], xa[mt][3], bf.x, bf.y);
        mma16816(pa[mt][1], xa[mt][0], xa[mt][1], xa[mt][2], xa[mt][3], bf.z, bf.w);
      }
#pragma unroll
      for (int mt = 0; mt < 4; ++mt)
#pragma unroll
        for (int tn = 0; tn < 2; ++tn) {
          int col = wid * 64 + pq * 16 + tn * 8 + lc2;
          int row0 = mt * 16 + lr;
          *(__half2*)(sm + OF_A + swA(row0, col * 2)) =
              __floats2half2_rn(fmaxf(pa[mt][tn][0], 0.f), fmaxf(pa[mt][tn][1], 0.f));
          *(__half2*)(sm + OF_A + swA(row0 + 8, col * 2)) =
              __floats2half2_rn(fmaxf(pa[mt][tn][2], 0.f), fmaxf(pa[mt][tn][3], 0.f));
        }
    }
  }
  __syncthreads();   // h1 complete (also orders s_part zeroing); A-tile read-only hereafter

  const float* b2 = (g < 3) ? (p.ent_b2 + m * 512) : p.pad_b2;
  float* sp = (float*)(sm + OF_P);

  // ---- all four nq quarters in one CTA, barrier-free ----
  for (int nq = 0; nq < 4; ++nq) {
    float acc[2][4][4];
#pragma unroll
    for (int mt = 0; mt < 2; ++mt)
#pragma unroll
      for (int nt = 0; nt < 4; ++nt)
#pragma unroll
        for (int i = 0; i < 4; ++i) acc[mt][nt][i] = 0.f;

    const char* wbase = (const char*)g_w2 +
        (size_t)(m * 4 + nq) * 131072 + nw * 1024 + lane * 16;
    uint4 bc0, bc1;
    if (nq == 0) { bc0 = pb0; bc1 = pb1; }
    else {
      bc0 = *(const uint4*)(wbase);
      bc1 = *(const uint4*)(wbase + 512);
    }
    uint32_t Ac0[4], Ac1[4], An0[4], An1[4];
    ldsm4(smb + OF_A + swA(mw * 32 + ag_r, ag_k * 2), Ac0[0], Ac0[1], Ac0[2], Ac0[3]);
    ldsm4(smb + OF_A + swA(mw * 32 + 16 + ag_r, ag_k * 2), Ac1[0], Ac1[1], Ac1[2], Ac1[3]);
#pragma unroll 8
    for (int kt = 0; kt < 32; ++kt) {
      uint4 bn0, bn1;
      if (kt < 31) {
        bn0 = *(const uint4*)(wbase + (kt + 1) * 4096);
        bn1 = *(const uint4*)(wbase + (kt + 1) * 4096 + 512);
        ldsm4(smb + OF_A + swA(mw * 32 + ag_r, ((kt + 1) * 16 + ag_k) * 2),
              An0[0], An0[1], An0[2], An0[3]);
        ldsm4(smb + OF_A + swA(mw * 32 + 16 + ag_r, ((kt + 1) * 16 + ag_k) * 2),
              An1[0], An1[1], An1[2], An1[3]);
      }
      mma16816(acc[0][0], Ac0[0], Ac0[1], Ac0[2], Ac0[3], bc0.x, bc0.y);
      mma16816(acc[1][0], Ac1[0], Ac1[1], Ac1[2], Ac1[3], bc0.x, bc0.y);
      mma16816(acc[0][1], Ac0[0], Ac0[1], Ac0[2], Ac0[3], bc0.z, bc0.w);
      mma16816(acc[1][1], Ac1[0], Ac1[1], Ac1[2], Ac1[3], bc0.z, bc0.w);
      mma16816(acc[0][2], Ac0[0], Ac0[1], Ac0[2], Ac0[3], bc1.x, bc1.y);
      mma16816(acc[1][2], Ac1[0], Ac1[1], Ac1[2], Ac1[3], bc1.x, bc1.y);
      mma16816(acc[0][3], Ac0[0], Ac0[1], Ac0[2], Ac0[3], bc1.z, bc1.w);
      mma16816(acc[1][3], Ac1[0], Ac1[1], Ac1[2], Ac1[3], bc1.z, bc1.w);
      bc0 = bn0; bc1 = bn1;
#pragma unroll
      for (int i = 0; i < 4; ++i) { Ac0[i] = An0[i]; Ac1[i] = An1[i]; }
    }

    // ---- heads B frags: issue LDGs early ----
    const uint4* hf = (const uint4*)((const char*)g_hd +
        (size_t)((m * 4 + nq) * 4 + nw) * 2048) + lane;
    uint4 h00 = hf[0], h01 = hf[32];
    uint4 h10 = hf[64], h11 = hf[96];

    // ---- h2 (bias+relu) -> A-frags IN REGISTERS ----
    uint32_t afh[2][2][4];
#pragma unroll
    for (int q = 0; q < 2; ++q) {
      int ce = nq * 128 + nw * 32 + q * 16 + lc2;
      float be0 = __ldg(b2 + ce),     be1 = __ldg(b2 + ce + 1);
      float bo0 = __ldg(b2 + ce + 8), bo1 = __ldg(b2 + ce + 9);
#pragma unroll
      for (int mt = 0; mt < 2; ++mt) {
        afh[mt][q][0] = packrelu(acc[mt][2 * q][0] + be0, acc[mt][2 * q][1] + be1);
        afh[mt][q][1] = packrelu(acc[mt][2 * q][2] + be0, acc[mt][2 * q][3] + be1);
        afh[mt][q][2] = packrelu(acc[mt][2 * q + 1][0] + bo0, acc[mt][2 * q + 1][1] + bo1);
        afh[mt][q][3] = packrelu(acc[mt][2 * q + 1][2] + bo0, acc[mt][2 * q + 1][3] + bo1);
      }
    }

    // ---- heads GEMM from registers ----
    float hacc[2][3][4];
#pragma unroll
    for (int mt = 0; mt < 2; ++mt)
#pragma unroll
      for (int nt = 0; nt < 3; ++nt)
#pragma unroll
        for (int i = 0; i < 4; ++i) hacc[mt][nt][i] = 0.f;
#pragma unroll
    for (int mt = 0; mt < 2; ++mt) {
      mma16816(hacc[mt][0], afh[mt][0][0], afh[mt][0][1], afh[mt][0][2], afh[mt][0][3], h00.x, h00.y);
      mma16816(hacc[mt][1], afh[mt][0][0], afh[mt][0][1], afh[mt][0][2], afh[mt][0][3], h00.z, h00.w);
      mma16816(hacc[mt][2], afh[mt][0][0], afh[mt][0][1], afh[mt][0][2], afh[mt][0][3], h01.x, h01.y);
      mma16816(hacc[mt][0], afh[mt][1][0], afh[mt][1][1], afh[mt][1][2], afh[mt][1][3], h10.x, h10.y);
      mma16816(hacc[mt][1], afh[mt][1][0], afh[mt][1][1], afh[mt][1][2], afh[mt][1][3], h10.z, h10.w);
      mma16816(hacc[mt][2], afh[mt][1][0], afh[mt][1][1], afh[mt][1][2], afh[mt][1][3], h11.x, h11.y);
    }

    // ---- reduce into SMEM s_part ----
#pragma unroll
    for (int mt = 0; mt < 2; ++mt)
#pragma unroll
      for (int nt = 0; nt < 3; ++nt) {
        int col = nt * 8 + lc2;
        if (col < 22) {
          int row0 = mw * 32 + mt * 16 + lr;
          atomicAdd(sp + row0 * 24 + col,           hacc[mt][nt][0]);
          atomicAdd(sp + row0 * 24 + col + 1,       hacc[mt][nt][1]);
          atomicAdd(sp + (row0 + 8) * 24 + col,     hacc[mt][nt][2]);
          atomicAdd(sp + (row0 + 8) * 24 + col + 1, hacc[mt][nt][3]);
        }
      }
  }
  __syncthreads();

  // ---- single non-atomic store of head sums ----
  for (int i = t; i < 64 * 22; i += NTH) {
    int s = i / 22, c = i - s * 22;
    g_part[((size_t)g * 32768 + s0 + s) * 22 + c] = sp[s * 24 + c];
  }
}

__global__ void epilogue_kernel(PE p, int B) {
  int s = blockIdx.x * blockDim.x + threadIdx.x;
  if (s >= B) return;
  float hd[9][22];
#pragma unroll
  for (int q = 0; q < 9; ++q) {
    const float* pp = g_part + ((size_t)q * 32768 + s) * 22;
#pragma unroll
    for (int c = 0; c < 22; ++c) hd[q][c] = pp[c];
  }
  float mx = -1e30f;
#pragma unroll
  for (int q = 3; q < 9; ++q) mx = fmaxf(mx, hd[q][21]);
  float den = 0.f, agg[21];
#pragma unroll
  for (int c = 0; c < 21; ++c) agg[c] = 0.f;
#pragma unroll
  for (int q = 3; q < 9; ++q) {
    float w = expf(hd[q][21] - mx);
    den += w;
#pragma unroll
    for (int c = 0; c < 21; ++c) agg[c] = fmaf(w, hd[q][c], agg[c]);
  }
  float inv = 1.f / den;

  float* o = p.out + (size_t)s * 105;
  float pos[4][3], coef[4][9], cov[4][9];
  for (int e = 0; e < 3; ++e) {
    for (int d = 0; d < 3; ++d) pos[e][d]  = hd[e][d] + p.ent_bpos[e * 3 + d];
    for (int c = 0; c < 9; ++c) coef[e][c] = hd[e][3 + c] + p.ent_bc[e * 9 + c];
    for (int c = 0; c < 9; ++c) cov[e][c]  = softplusf(hd[e][12 + c] + p.ent_bv[e * 9 + c]);
  }
  for (int d = 0; d < 3; ++d) pos[3][d]  = agg[d] * inv + p.b_bpos[d];
  for (int c = 0; c < 9; ++c) coef[3][c] = agg[3 + c] * inv + p.b_bc[c];
  for (int c = 0; c < 9; ++c) cov[3][c]  = softplusf(agg[12 + c] * inv + p.b_bv[c]);
  for (int i = 0; i < 4; ++i) {
    float x = pos[i][0], y = pos[i][1], z = pos[i][2];
    for (int c = 0; c < 9; ++c) o[i * 24 + c]     = coef[i][c];
    for (int c = 0; c < 9; ++c) o[i * 24 + 9 + c] = cov[i][c];
    o[i * 24 + 18] = (4096.f - x) * 1e-3f;
    o[i * 24 + 19] = (4096.f + x) * 1e-3f;
    o[i * 24 + 20] = (5120.f - y) * 1e-3f;
    o[i * 24 + 21] = (5120.f + y) * 1e-3f;
    o[i * 24 + 22] = z * 1e-3f;
    o[i * 24 + 23] = (2044.f - z) * 1e-3f;
  }
  const int iu[6] = {0, 0, 0, 1, 1, 2}, ju[6] = {1, 2, 3, 2, 3, 3};
  for (int q = 0; q < 6; ++q) {
    int i = iu[q], j = ju[q];
    float d2 = 0.f, cd = 0.f;
    for (int d = 0; d < 3; ++d) { float df = pos[i][d] - pos[j][d]; d2 = fmaf(df, df, d2); }
    for (int c = 0; c < 9; ++c) cd = fmaf(coef[i][c], coef[j][c], cd);
    o[96 + q] = expf(-2.f * d2) * cd;
  }
  for (int d = 0; d < 3; ++d) {
    float ga = p.gs_b[d];
    for (int k = 0; k < 10; ++k)
      ga = fmaf(p.tokens[(size_t)s * 100 + 90 + k], p.gs_W[k * 3 + d], ga);
    o[102 + d] = ga;
  }
}

extern "C" void kernel_launch(void* const* d_in, const int* in_sizes, int n_in,
                              void* d_out, int out_size) {
  pack_kernel<<<512, 256>>>(
      (const float*)d_in[3],  (const float*)d_in[13],
      (const float*)d_in[1],  (const float*)d_in[2],
      (const float*)d_in[11], (const float*)d_in[12],
      (const float*)d_in[5],  (const float*)d_in[7],  (const float*)d_in[9],
      (const float*)d_in[17], (const float*)d_in[19], (const float*)d_in[21],
      (const float*)d_in[15]);

  int B = in_sizes[0] / 100;

  PM pm;
  pm.tokens = (const float*)d_in[0];
  pm.ent_b2 = (const float*)d_in[4];
  pm.pad_b2 = (const float*)d_in[14];
  cudaFuncSetAttribute(spectral_mma_kernel, cudaFuncAttributeMaxDynamicSharedMemorySize, SMEM_SZ);
  dim3 grid(B / 64, 9, 1);
  spectral_mma_kernel<<<grid, NTH, SMEM_SZ>>>(pm);

  PE pe;
  pe.tokens = (const float*)d_in[0];
  pe.ent_bpos = (const float*)d_in[6];
  pe.ent_bc = (const float*)d_in[8];
  pe.ent_bv = (const float*)d_in[10];
  pe.b_bpos = (const float*)d_in[18];
  pe.b_bc = (const float*)d_in[20];
  pe.b_bv = (const float*)d_in[22];
  pe.gs_W = (const float*)d_in[23];
  pe.gs_b = (const float*)d_in[24];
  pe.out = (float*)d_out;
  epilogue_kernel<<<(B + 127) / 128, 128>>>(pe, B);
}